// round 13
// baseline (speedup 1.0000x reference)
#include <cuda_runtime.h>
#include <cuda_bf16.h>
#include <math.h>

// Problem constants
#define BB 2048
#define TT 256
#define FF 64
#define HH 32
#define G3 96   // 3*H

typedef unsigned long long ull;

// Scratch for input-gate projections xg[t][b][96]  (201 MB, static device alloc)
__device__ float g_xg[(size_t)TT * BB * G3];

// ---- f32x2 packed helpers (sm_100+ PTX) -----------------------------------
__device__ __forceinline__ ull ffma2(ull a, ull b, ull c) {
    ull d;
    asm("fma.rn.f32x2 %0, %1, %2, %3;" : "=l"(d) : "l"(a), "l"(b), "l"(c));
    return d;
}
__device__ __forceinline__ ull pack2(float lo, float hi) {
    ull d;
    asm("mov.b64 %0, {%1, %2};" : "=l"(d) : "f"(lo), "f"(hi));
    return d;
}
// Hardware tanh (MUFU.TANH, sm_75+; ~5e-4 max rel err)
__device__ __forceinline__ float tanh_apx(float x) {
    float y;
    asm("tanh.approx.f32 %0, %1;" : "=f"(y) : "f"(x));
    return y;
}

// ---------------------------------------------------------------------------
// Kernel 1: xg[(t*B + b)*96 + g] = sum_k x[b,t,k] * W_ih[g,k] + b_ih[g]
// Block tile: 128 b-rows x 96 gate-cols at fixed t; 192 threads, each 8x8.
// K staged in two 32-wide halves (static smem <= 48KB). fma.rn.f32x2 math.
// ---------------------------------------------------------------------------
__global__ __launch_bounds__(192) void xg_gemm_kernel(
    const float* __restrict__ x,      // [B, T, F]
    const float* __restrict__ W_ih,   // [96, 64]
    const float* __restrict__ b_ih)   // [96]
{
    __shared__ float As[32][136];  // [k][row] row stride 544B (16B-mult)
    __shared__ float Ws[32][100];  // [k][g]   row stride 400B (16B-mult)

    const int t  = blockIdx.y;
    const int b0 = blockIdx.x * 128;
    const int tid = threadIdx.x;        // 0..191
    const int rg = tid & 15;            // rows rg*8 .. rg*8+7
    const int cg = tid >> 4;            // cols cg*8 .. cg*8+7 (cg 0..11)

    // acc2[u][v]: packed pair = cols (cg*8+2v, cg*8+2v+1) for row rg*8+u
    ull acc2[8][4];
#pragma unroll
    for (int v = 0; v < 4; v++) {
        ull bias = pack2(b_ih[cg * 8 + 2 * v], b_ih[cg * 8 + 2 * v + 1]);
#pragma unroll
        for (int u = 0; u < 8; u++)
            acc2[u][v] = bias;
    }

#pragma unroll
    for (int kh = 0; kh < 2; kh++) {
        if (kh) __syncthreads();   // protect smem reuse
        // Stage x half-tile: As[k][row] = x[(b0+row), t, kh*32+k]
        for (int idx = tid; idx < 32 * 128; idx += 192) {
            int row = idx >> 5;
            int k   = idx & 31;
            As[k][row] = x[((size_t)(b0 + row) * TT + t) * FF + kh * 32 + k];
        }
        // Stage W half: Ws[k][g] = W_ih[g*64 + kh*32 + k]
        for (int idx = tid; idx < 32 * 96; idx += 192) {
            int g = idx >> 5;
            int k = idx & 31;
            Ws[k][g] = W_ih[g * FF + kh * 32 + k];
        }
        __syncthreads();

#pragma unroll
        for (int k = 0; k < 32; k++) {
            float4 a0 = *reinterpret_cast<const float4*>(&As[k][rg * 8]);
            float4 a1 = *reinterpret_cast<const float4*>(&As[k][rg * 8 + 4]);
            ulonglong2 wa = *reinterpret_cast<const ulonglong2*>(&Ws[k][cg * 8]);
            ulonglong2 wb = *reinterpret_cast<const ulonglong2*>(&Ws[k][cg * 8 + 4]);
            ull wv[4] = {wa.x, wa.y, wb.x, wb.y};
            float av[8] = {a0.x, a0.y, a0.z, a0.w, a1.x, a1.y, a1.z, a1.w};
#pragma unroll
            for (int u = 0; u < 8; u++) {
                ull ad = pack2(av[u], av[u]);
#pragma unroll
                for (int v = 0; v < 4; v++)
                    acc2[u][v] = ffma2(ad, wv[v], acc2[u][v]);
            }
        }
    }

    // Store: packed pairs are bit-identical to consecutive floats; 32B-aligned.
#pragma unroll
    for (int u = 0; u < 8; u++) {
        size_t base = ((size_t)t * BB + (b0 + rg * 8 + u)) * G3 + cg * 8;
        ulonglong2 s0 = make_ulonglong2(acc2[u][0], acc2[u][1]);
        ulonglong2 s1 = make_ulonglong2(acc2[u][2], acc2[u][3]);
        *reinterpret_cast<ulonglong2*>(&g_xg[base])     = s0;
        *reinterpret_cast<ulonglong2*>(&g_xg[base + 4]) = s1;
    }
}

// ---------------------------------------------------------------------------
// Kernel 2: recurrent GRU. One warp per batch element; lane i owns hidden
// unit i. W_hh rows {i, 32+i, 64+i} in registers. h broadcast via shfl.
// MUFU.TANH-based activations; streamed (.cs) xg loads with dist-1 prefetch.
// ---------------------------------------------------------------------------
__global__ __launch_bounds__(128) void gru_recurrent_kernel(
    const float* __restrict__ W_hh,    // [96, 32]
    const float* __restrict__ b_hh,    // [96]
    const float* __restrict__ W_head,  // [32]
    const float* __restrict__ b_head,  // [1]
    float* __restrict__ out)           // [B]
{
    const int warp = (blockIdx.x * blockDim.x + threadIdx.x) >> 5;
    const int lane = threadIdx.x & 31;
    if (warp >= BB) return;
    const int b = warp;

    float wr[HH], wz[HH], wn[HH];
#pragma unroll
    for (int j = 0; j < HH; j++) {
        wr[j] = W_hh[(0 * HH + lane) * HH + j];
        wz[j] = W_hh[(1 * HH + lane) * HH + j];
        wn[j] = W_hh[(2 * HH + lane) * HH + j];
    }
    const float bhr = b_hh[lane];
    const float bhz = b_hh[HH + lane];
    const float bhn = b_hh[2 * HH + lane];

    float h = 0.0f;
    const float* xgp = g_xg + (size_t)b * G3;

    // Prefetch t=0 (streaming: read-once data)
    float pxr = __ldcs(&xgp[lane]);
    float pxz = __ldcs(&xgp[HH + lane]);
    float pxn = __ldcs(&xgp[2 * HH + lane]);

    for (int t = 0; t < TT; t++) {
        float xr = pxr, xz = pxz, xn = pxn;

        // Issue next step's loads NOW (h-independent) to hide DRAM latency.
        xgp += (size_t)BB * G3;
        const float* pf = (t + 1 < TT) ? xgp : (xgp - (size_t)BB * G3);
        pxr = __ldcs(&pf[lane]);
        pxz = __ldcs(&pf[HH + lane]);
        pxn = __ldcs(&pf[2 * HH + lane]);

        // h @ W_hh^T with split (even/odd) accumulation chains
        float hr0 = bhr, hz0 = bhz, hn0 = bhn;
        float hr1 = 0.0f, hz1 = 0.0f, hn1 = 0.0f;
#pragma unroll
        for (int j = 0; j < HH; j += 2) {
            float hj0 = __shfl_sync(0xffffffffu, h, j);
            float hj1 = __shfl_sync(0xffffffffu, h, j + 1);
            hr0 = fmaf(wr[j], hj0, hr0);
            hz0 = fmaf(wz[j], hj0, hz0);
            hn0 = fmaf(wn[j], hj0, hn0);
            hr1 = fmaf(wr[j + 1], hj1, hr1);
            hz1 = fmaf(wz[j + 1], hj1, hz1);
            hn1 = fmaf(wn[j + 1], hj1, hn1);
        }
        float hr = hr0 + hr1;
        float hz = hz0 + hz1;
        float hn = hn0 + hn1;

        // sigmoid(a) = 0.5*tanh(a/2) + 0.5  (MUFU.TANH)
        float r = fmaf(tanh_apx(0.5f * (xr + hr)), 0.5f, 0.5f);
        float z = fmaf(tanh_apx(0.5f * (xz + hz)), 0.5f, 0.5f);
        float n = tanh_apx(fmaf(r, hn, xn));
        h = fmaf(z, h - n, n);        // (1-z)*n + z*h
    }

    // Head: y = sigmoid(h . W_head + b_head)
    float v = h * W_head[lane];
#pragma unroll
    for (int off = 16; off > 0; off >>= 1)
        v += __shfl_xor_sync(0xffffffffu, v, off);
    if (lane == 0)
        out[b] = fmaf(tanh_apx(0.5f * (v + b_head[0])), 0.5f, 0.5f);
}

// ---------------------------------------------------------------------------
extern "C" void kernel_launch(void* const* d_in, const int* in_sizes, int n_in,
                              void* d_out, int out_size)
{
    const float* x      = (const float*)d_in[0];  // [B,T,F]
    const float* W_ih   = (const float*)d_in[1];  // [96,64]
    const float* W_hh   = (const float*)d_in[2];  // [96,32]
    const float* b_ih   = (const float*)d_in[3];  // [96]
    const float* b_hh   = (const float*)d_in[4];  // [96]
    const float* W_head = (const float*)d_in[5];  // [1,32]
    const float* b_head = (const float*)d_in[6];  // [1]
    float* out = (float*)d_out;                   // [B,1] = 2048 floats

    dim3 g1(BB / 128, TT);
    xg_gemm_kernel<<<g1, 192>>>(x, W_ih, b_ih);

    gru_recurrent_kernel<<<(BB * 32) / 128, 128>>>(W_hh, b_hh, W_head, b_head, out);
}

// round 14
// speedup vs baseline: 1.2387x; 1.2387x over previous
#include <cuda_runtime.h>
#include <cuda_bf16.h>
#include <math.h>

// Problem constants
#define BB 2048
#define TT 256
#define FF 64
#define HH 32
#define G3 96   // 3*H

typedef unsigned long long ull;

// Scratch for input-gate projections xg[t][b][96]  (201 MB, static device alloc)
__device__ float g_xg[(size_t)TT * BB * G3];

// ---- f32x2 packed helpers (sm_100+ PTX) -----------------------------------
__device__ __forceinline__ ull ffma2(ull a, ull b, ull c) {
    ull d;
    asm("fma.rn.f32x2 %0, %1, %2, %3;" : "=l"(d) : "l"(a), "l"(b), "l"(c));
    return d;
}
__device__ __forceinline__ ull add2(ull a, ull b) {
    ull d;
    asm("add.rn.f32x2 %0, %1, %2;" : "=l"(d) : "l"(a), "l"(b));
    return d;
}
__device__ __forceinline__ ull pack2(float lo, float hi) {
    ull d;
    asm("mov.b64 %0, {%1, %2};" : "=l"(d) : "f"(lo), "f"(hi));
    return d;
}
__device__ __forceinline__ float unpack_sum(ull p) {
    float lo, hi;
    asm("mov.b64 {%0, %1}, %2;" : "=f"(lo), "=f"(hi) : "l"(p));
    return lo + hi;
}
// Hardware tanh (MUFU.TANH, sm_75+; ~5e-4 max rel err)
__device__ __forceinline__ float tanh_apx(float x) {
    float y;
    asm("tanh.approx.f32 %0, %1;" : "=f"(y) : "f"(x));
    return y;
}

// ---------------------------------------------------------------------------
// Kernel 1 (reverted to measured-191us R4 version):
// xg[(t*B + b)*96 + g] = sum_k x[b,t,k] * W_ih[g,k] + b_ih[g]
// Tile: 64 b-rows x 96 gate-cols at fixed t. 192 threads, each 4 rows x 8 cols.
// ---------------------------------------------------------------------------
__global__ __launch_bounds__(192) void xg_gemm_kernel(
    const float* __restrict__ x,      // [B, T, F]
    const float* __restrict__ W_ih,   // [96, 64]
    const float* __restrict__ b_ih)   // [96]
{
    __shared__ float As[64][68];   // [k][row]  row stride 272B (16B-mult)
    __shared__ float Ws[64][100];  // [k][g]    row stride 400B (16B-mult)

    const int t  = blockIdx.y;
    const int b0 = blockIdx.x * 64;
    const int tid = threadIdx.x;        // 0..191
    const int rg = tid & 15;            // rows rg*4 .. rg*4+3
    const int cg = tid >> 4;            // cols cg*8 .. cg*8+7

    for (int idx = tid; idx < 64 * 64; idx += 192) {
        int row = idx >> 6;
        int k   = idx & 63;
        As[k][row] = x[((size_t)(b0 + row) * TT + t) * FF + k];
    }
    for (int idx = tid; idx < G3 * FF; idx += 192) {
        int g = idx >> 6;
        int k = idx & 63;
        Ws[k][g] = W_ih[idx];
    }
    __syncthreads();

    // acc2[u][v]: packed pair = cols (cg*8+2v, cg*8+2v+1) for row rg*4+u
    ull acc2[4][4];
#pragma unroll
    for (int v = 0; v < 4; v++) {
        ull bias = pack2(b_ih[cg * 8 + 2 * v], b_ih[cg * 8 + 2 * v + 1]);
#pragma unroll
        for (int u = 0; u < 4; u++)
            acc2[u][v] = bias;
    }

#pragma unroll
    for (int k = 0; k < 64; k++) {
        float4 a = *reinterpret_cast<const float4*>(&As[k][rg * 4]);
        ulonglong2 wa = *reinterpret_cast<const ulonglong2*>(&Ws[k][cg * 8]);
        ulonglong2 wb = *reinterpret_cast<const ulonglong2*>(&Ws[k][cg * 8 + 4]);
        ull wv[4] = {wa.x, wa.y, wb.x, wb.y};
        ull ad[4] = {pack2(a.x, a.x), pack2(a.y, a.y),
                     pack2(a.z, a.z), pack2(a.w, a.w)};
#pragma unroll
        for (int u = 0; u < 4; u++)
#pragma unroll
            for (int v = 0; v < 4; v++)
                acc2[u][v] = ffma2(ad[u], wv[v], acc2[u][v]);
    }

#pragma unroll
    for (int u = 0; u < 4; u++) {
        size_t base = ((size_t)t * BB + (b0 + rg * 4 + u)) * G3 + cg * 8;
        ulonglong2 s0 = make_ulonglong2(acc2[u][0], acc2[u][1]);
        ulonglong2 s1 = make_ulonglong2(acc2[u][2], acc2[u][3]);
        *reinterpret_cast<ulonglong2*>(&g_xg[base])     = s0;
        *reinterpret_cast<ulonglong2*>(&g_xg[base + 4]) = s1;
    }
}

// ---------------------------------------------------------------------------
// Kernel 2: recurrent GRU. One warp per batch element; lane i owns hidden
// unit i. NO SHFL: h broadcast via per-warp double-buffered smem row
// (1 STS + 1 syncwarp + 8 broadcast LDS.128 per step). hh-matvec done with
// fma.rn.f32x2 packed over j-pairs (48 FFMA2 instead of 96 FFMA), packed h
// operands come directly from the 16B smem loads. MUFU.TANH activations.
// ---------------------------------------------------------------------------
__global__ __launch_bounds__(128) void gru_recurrent_kernel(
    const float* __restrict__ W_hh,    // [96, 32]
    const float* __restrict__ b_hh,    // [96]
    const float* __restrict__ W_head,  // [32]
    const float* __restrict__ b_head,  // [1]
    float* __restrict__ out)           // [B]
{
    __shared__ __align__(16) float h_buf[4][2][HH];  // [warp][parity][unit]

    const int warp   = (blockIdx.x * blockDim.x + threadIdx.x) >> 5;
    const int wlocal = (threadIdx.x >> 5) & 3;
    const int lane   = threadIdx.x & 31;
    if (warp >= BB) return;
    const int b = warp;

    // Pre-pack W_hh rows {lane, 32+lane, 64+lane} into j-pair f32x2 registers.
    ull wrp[16], wzp[16], wnp[16];
#pragma unroll
    for (int j = 0; j < 16; j++) {
        const float* r0 = &W_hh[(0 * HH + lane) * HH + 2 * j];
        const float* r1 = &W_hh[(1 * HH + lane) * HH + 2 * j];
        const float* r2 = &W_hh[(2 * HH + lane) * HH + 2 * j];
        wrp[j] = pack2(r0[0], r0[1]);
        wzp[j] = pack2(r1[0], r1[1]);
        wnp[j] = pack2(r2[0], r2[1]);
    }
    const float bhr = b_hh[lane];
    const float bhz = b_hh[HH + lane];
    const float bhn = b_hh[2 * HH + lane];

    float h = 0.0f;
    h_buf[wlocal][0][lane] = 0.0f;
    __syncwarp();

    const float* xgp = g_xg + (size_t)b * G3;
    float pxr = __ldcs(&xgp[lane]);
    float pxz = __ldcs(&xgp[HH + lane]);
    float pxn = __ldcs(&xgp[2 * HH + lane]);

    for (int t = 0; t < TT; t++) {
        const int par = t & 1;
        float xr = pxr, xz = pxz, xn = pxn;

        // Prefetch next step's xg (h-independent).
        xgp += (size_t)BB * G3;
        const float* pf = (t + 1 < TT) ? xgp : (xgp - (size_t)BB * G3);
        pxr = __ldcs(&pf[lane]);
        pxz = __ldcs(&pf[HH + lane]);
        pxn = __ldcs(&pf[2 * HH + lane]);

        // h @ W_hh^T: packed j-pairs, two chains per gate (depth 8).
        ull ar0 = pack2(bhr, 0.0f), az0 = pack2(bhz, 0.0f), an0 = pack2(bhn, 0.0f);
        ull ar1 = pack2(0.0f, 0.0f), az1 = ar1, an1 = ar1;
        const ulonglong2* hp =
            reinterpret_cast<const ulonglong2*>(h_buf[wlocal][par]);
#pragma unroll
        for (int c = 0; c < 8; c++) {
            ulonglong2 hq = hp[c];     // broadcast LDS.128: h[4c..4c+3] packed
            ar0 = ffma2(wrp[2 * c],     hq.x, ar0);
            az0 = ffma2(wzp[2 * c],     hq.x, az0);
            an0 = ffma2(wnp[2 * c],     hq.x, an0);
            ar1 = ffma2(wrp[2 * c + 1], hq.y, ar1);
            az1 = ffma2(wzp[2 * c + 1], hq.y, az1);
            an1 = ffma2(wnp[2 * c + 1], hq.y, an1);
        }
        float hr = unpack_sum(add2(ar0, ar1));
        float hz = unpack_sum(add2(az0, az1));
        float hn = unpack_sum(add2(an0, an1));

        // sigmoid(a) = 0.5*tanh(a/2) + 0.5  (MUFU.TANH)
        float r = fmaf(tanh_apx(0.5f * (xr + hr)), 0.5f, 0.5f);
        float z = fmaf(tanh_apx(0.5f * (xz + hz)), 0.5f, 0.5f);
        float n = tanh_apx(fmaf(r, hn, xn));
        h = fmaf(z, h - n, n);         // (1-z)*n + z*h

        h_buf[wlocal][par ^ 1][lane] = h;
        __syncwarp();
    }

    // Head: y = sigmoid(h . W_head + b_head)
    float v = h * W_head[lane];
#pragma unroll
    for (int off = 16; off > 0; off >>= 1)
        v += __shfl_xor_sync(0xffffffffu, v, off);
    if (lane == 0)
        out[b] = fmaf(tanh_apx(0.5f * (v + b_head[0])), 0.5f, 0.5f);
}

// ---------------------------------------------------------------------------
extern "C" void kernel_launch(void* const* d_in, const int* in_sizes, int n_in,
                              void* d_out, int out_size)
{
    const float* x      = (const float*)d_in[0];  // [B,T,F]
    const float* W_ih   = (const float*)d_in[1];  // [96,64]
    const float* W_hh   = (const float*)d_in[2];  // [96,32]
    const float* b_ih   = (const float*)d_in[3];  // [96]
    const float* b_hh   = (const float*)d_in[4];  // [96]
    const float* W_head = (const float*)d_in[5];  // [1,32]
    const float* b_head = (const float*)d_in[6];  // [1]
    float* out = (float*)d_out;                   // [B,1] = 2048 floats

    dim3 g1(BB / 64, TT);
    xg_gemm_kernel<<<g1, 192>>>(x, W_ih, b_ih);

    gru_recurrent_kernel<<<(BB * 32) / 128, 128>>>(W_hh, b_hh, W_head, b_head, out);
}

// round 15
// speedup vs baseline: 1.3586x; 1.0968x over previous
#include <cuda_runtime.h>
#include <cuda_fp16.h>
#include <math.h>

// Problem constants
#define BB 2048
#define TT 256
#define FF 64
#define HH 32
#define G3 96   // 3*H

typedef unsigned long long ull;

// Scratch for input-gate projections xg[t][b][96] in fp16 (100 MB static).
// fp16 halves the DRAM stream that bounds both kernels; |xg| <~ 30 fits e5m10
// with ~5e-4 rel err, which the contractive GRU maps to ~1e-4 output error.
__device__ __half g_xg[(size_t)TT * BB * G3];

// ---- f32x2 packed helpers (sm_100+ PTX) -----------------------------------
__device__ __forceinline__ ull ffma2(ull a, ull b, ull c) {
    ull d;
    asm("fma.rn.f32x2 %0, %1, %2, %3;" : "=l"(d) : "l"(a), "l"(b), "l"(c));
    return d;
}
__device__ __forceinline__ ull pack2(float lo, float hi) {
    ull d;
    asm("mov.b64 %0, {%1, %2};" : "=l"(d) : "f"(lo), "f"(hi));
    return d;
}
__device__ __forceinline__ float2 unpack2f(ull p) {
    float2 r;
    asm("mov.b64 {%0, %1}, %2;" : "=f"(r.x), "=f"(r.y) : "l"(p));
    return r;
}
// Hardware tanh (MUFU.TANH; ~5e-4 max rel err)
__device__ __forceinline__ float tanh_apx(float x) {
    float y;
    asm("tanh.approx.f32 %0, %1;" : "=f"(y) : "f"(x));
    return y;
}

// ---------------------------------------------------------------------------
// Kernel 1 (R4 structure, measured 170-191us): fp16 output now.
// xg[(t*B + b)*96 + g] = sum_k x[b,t,k] * W_ih[g,k] + b_ih[g]
// Tile: 64 b-rows x 96 gate-cols at fixed t. 192 threads, each 4 rows x 8 cols.
// ---------------------------------------------------------------------------
__global__ __launch_bounds__(192) void xg_gemm_kernel(
    const float* __restrict__ x,      // [B, T, F]
    const float* __restrict__ W_ih,   // [96, 64]
    const float* __restrict__ b_ih)   // [96]
{
    __shared__ float As[64][68];   // [k][row]  row stride 272B (16B-mult)
    __shared__ float Ws[64][100];  // [k][g]    row stride 400B (16B-mult)

    const int t  = blockIdx.y;
    const int b0 = blockIdx.x * 64;
    const int tid = threadIdx.x;        // 0..191
    const int rg = tid & 15;            // rows rg*4 .. rg*4+3
    const int cg = tid >> 4;            // cols cg*8 .. cg*8+7

    for (int idx = tid; idx < 64 * 64; idx += 192) {
        int row = idx >> 6;
        int k   = idx & 63;
        As[k][row] = x[((size_t)(b0 + row) * TT + t) * FF + k];
    }
    for (int idx = tid; idx < G3 * FF; idx += 192) {
        int g = idx >> 6;
        int k = idx & 63;
        Ws[k][g] = W_ih[idx];
    }
    __syncthreads();

    // acc2[u][v]: packed pair = cols (cg*8+2v, cg*8+2v+1) for row rg*4+u
    ull acc2[4][4];
#pragma unroll
    for (int v = 0; v < 4; v++) {
        ull bias = pack2(b_ih[cg * 8 + 2 * v], b_ih[cg * 8 + 2 * v + 1]);
#pragma unroll
        for (int u = 0; u < 4; u++)
            acc2[u][v] = bias;
    }

#pragma unroll
    for (int k = 0; k < 64; k++) {
        float4 a = *reinterpret_cast<const float4*>(&As[k][rg * 4]);
        ulonglong2 wa = *reinterpret_cast<const ulonglong2*>(&Ws[k][cg * 8]);
        ulonglong2 wb = *reinterpret_cast<const ulonglong2*>(&Ws[k][cg * 8 + 4]);
        ull wv[4] = {wa.x, wa.y, wb.x, wb.y};
        ull ad[4] = {pack2(a.x, a.x), pack2(a.y, a.y),
                     pack2(a.z, a.z), pack2(a.w, a.w)};
#pragma unroll
        for (int u = 0; u < 4; u++)
#pragma unroll
            for (int v = 0; v < 4; v++)
                acc2[u][v] = ffma2(ad[u], wv[v], acc2[u][v]);
    }

    // Convert to fp16 and store 8 halves (16B) per row.
#pragma unroll
    for (int u = 0; u < 4; u++) {
        size_t base = ((size_t)t * BB + (b0 + rg * 4 + u)) * G3 + cg * 8;
        unsigned int q[4];
#pragma unroll
        for (int v = 0; v < 4; v++) {
            float2 f = unpack2f(acc2[u][v]);
            __half2 h2 = __floats2half2_rn(f.x, f.y);
            q[v] = *reinterpret_cast<unsigned int*>(&h2);
        }
        uint4 s = make_uint4(q[0], q[1], q[2], q[3]);
        *reinterpret_cast<uint4*>(&g_xg[base]) = s;   // 16B-aligned
    }
}

// ---------------------------------------------------------------------------
// Kernel 2 (R4 shfl form — measured best): fp16 xg loads with dist-1 prefetch.
// One warp per batch element; lane i owns hidden unit i; W_hh rows in regs;
// h broadcast via shfl; MUFU.TANH activations.
// ---------------------------------------------------------------------------
__global__ __launch_bounds__(128) void gru_recurrent_kernel(
    const float* __restrict__ W_hh,    // [96, 32]
    const float* __restrict__ b_hh,    // [96]
    const float* __restrict__ W_head,  // [32]
    const float* __restrict__ b_head,  // [1]
    float* __restrict__ out)           // [B]
{
    const int warp = (blockIdx.x * blockDim.x + threadIdx.x) >> 5;
    const int lane = threadIdx.x & 31;
    if (warp >= BB) return;
    const int b = warp;

    float wr[HH], wz[HH], wn[HH];
#pragma unroll
    for (int j = 0; j < HH; j++) {
        wr[j] = W_hh[(0 * HH + lane) * HH + j];
        wz[j] = W_hh[(1 * HH + lane) * HH + j];
        wn[j] = W_hh[(2 * HH + lane) * HH + j];
    }
    const float bhr = b_hh[lane];
    const float bhz = b_hh[HH + lane];
    const float bhn = b_hh[2 * HH + lane];

    float h = 0.0f;
    const __half* xgp = g_xg + (size_t)b * G3;

    // Prefetch t=0 (default caching: k1-write -> k2-read can hit in L2)
    __half pxr = xgp[lane];
    __half pxz = xgp[HH + lane];
    __half pxn = xgp[2 * HH + lane];

    for (int t = 0; t < TT; t++) {
        float xr = __half2float(pxr);
        float xz = __half2float(pxz);
        float xn = __half2float(pxn);

        // Issue next step's loads NOW (h-independent) to hide DRAM latency.
        xgp += (size_t)BB * G3;
        const __half* pf = (t + 1 < TT) ? xgp : (xgp - (size_t)BB * G3);
        pxr = pf[lane];
        pxz = pf[HH + lane];
        pxn = pf[2 * HH + lane];

        // h @ W_hh^T with split (even/odd) accumulation chains
        float hr0 = bhr, hz0 = bhz, hn0 = bhn;
        float hr1 = 0.0f, hz1 = 0.0f, hn1 = 0.0f;
#pragma unroll
        for (int j = 0; j < HH; j += 2) {
            float hj0 = __shfl_sync(0xffffffffu, h, j);
            float hj1 = __shfl_sync(0xffffffffu, h, j + 1);
            hr0 = fmaf(wr[j], hj0, hr0);
            hz0 = fmaf(wz[j], hj0, hz0);
            hn0 = fmaf(wn[j], hj0, hn0);
            hr1 = fmaf(wr[j + 1], hj1, hr1);
            hz1 = fmaf(wz[j + 1], hj1, hz1);
            hn1 = fmaf(wn[j + 1], hj1, hn1);
        }
        float hr = hr0 + hr1;
        float hz = hz0 + hz1;
        float hn = hn0 + hn1;

        // sigmoid(a) = 0.5*tanh(a/2) + 0.5  (MUFU.TANH)
        float r = fmaf(tanh_apx(0.5f * (xr + hr)), 0.5f, 0.5f);
        float z = fmaf(tanh_apx(0.5f * (xz + hz)), 0.5f, 0.5f);
        float n = tanh_apx(fmaf(r, hn, xn));
        h = fmaf(z, h - n, n);        // (1-z)*n + z*h
    }

    // Head: y = sigmoid(h . W_head + b_head)
    float v = h * W_head[lane];
#pragma unroll
    for (int off = 16; off > 0; off >>= 1)
        v += __shfl_xor_sync(0xffffffffu, v, off);
    if (lane == 0)
        out[b] = fmaf(tanh_apx(0.5f * (v + b_head[0])), 0.5f, 0.5f);
}

// ---------------------------------------------------------------------------
extern "C" void kernel_launch(void* const* d_in, const int* in_sizes, int n_in,
                              void* d_out, int out_size)
{
    const float* x      = (const float*)d_in[0];  // [B,T,F]
    const float* W_ih   = (const float*)d_in[1];  // [96,64]
    const float* W_hh   = (const float*)d_in[2];  // [96,32]
    const float* b_ih   = (const float*)d_in[3];  // [96]
    const float* b_hh   = (const float*)d_in[4];  // [96]
    const float* W_head = (const float*)d_in[5];  // [1,32]
    const float* b_head = (const float*)d_in[6];  // [1]
    float* out = (float*)d_out;                   // [B,1] = 2048 floats

    dim3 g1(BB / 64, TT);
    xg_gemm_kernel<<<g1, 192>>>(x, W_ih, b_ih);

    gru_recurrent_kernel<<<(BB * 32) / 128, 128>>>(W_hh, b_hh, W_head, b_head, out);
}